// round 16
// baseline (speedup 1.0000x reference)
#include <cuda_runtime.h>
#include <cuda_bf16.h>
#include <math.h>
#include <stdint.h>

#define B_TOK 16384
#define D_IN  1024
#define H_DIM 512
#define O_DIM 256
#define E_NUM 8

// ---------------------------------------------------------------------------
// Split-bf16 storage format (all GEMM operands):
// row r of a [R][K] matrix occupies K*4 bytes; each 32-k block kb is 128 B:
//   [32 x bf16 hi | 32 x bf16 lo].  Element stride is thus 4 B, so all the
// float*-style pointer arithmetic of the tf32 kernel carries over unchanged.
// ---------------------------------------------------------------------------

// Scratch (__device__ globals; no allocation allowed)
__device__ __align__(16) unsigned char g_xr[(size_t)B_TOK * D_IN * 4];
__device__ __align__(16) unsigned char g_gw1t[(size_t)256 * 1024 * 4];
__device__ __align__(16) unsigned char g_gw2t[(size_t)128 * 256 * 4];
__device__ __align__(16) unsigned char g_w1cat[(size_t)E_NUM * 512 * 1024 * 4];
__device__ __align__(16) unsigned char g_w2t[(size_t)E_NUM * 512 * 512 * 4];
__device__ __align__(16) unsigned char g_w3cat[(size_t)256 * 4096 * 4];
__device__ __align__(16) unsigned char g_g1[(size_t)B_TOK * 256 * 4];
__device__ __align__(16) unsigned char g_g2[(size_t)B_TOK * 128 * 4];
__device__ float g_gates[(size_t)B_TOK * 8];
__device__ __align__(16) unsigned char g_h1s[(size_t)B_TOK * 4096 * 4];
__device__ __align__(16) unsigned char g_h2s[(size_t)B_TOK * 4096 * 4];

// ---------------------------------------------------------------------------
// Helpers
// ---------------------------------------------------------------------------
__device__ __forceinline__ void cpa16(uint32_t d, const void* s) {
    asm volatile("cp.async.cg.shared.global [%0], [%1], 16;" :: "r"(d), "l"(s));
}
__device__ __forceinline__ void cpa16b(uint32_t d, const void* s) {
    asm volatile("cp.async.cg.shared.global [%0+16384], [%1], 16;" :: "r"(d), "l"(s));
}
template <int IMM>
__device__ __forceinline__ uint4 lds128(uint32_t addr) {
    uint4 v;
    asm volatile("ld.shared.v4.u32 {%0,%1,%2,%3}, [%4+%5];"
                 : "=r"(v.x), "=r"(v.y), "=r"(v.z), "=r"(v.w)
                 : "r"(addr), "n"(IMM));
    return v;
}
// Per-row 16B-chunk permutation (identical to the tf32 kernel); fperm(r+8)==fperm(r).
__device__ __forceinline__ uint32_t fperm(uint32_t r) {
    return ((r & 1u) << 2) | ((r >> 1) & 3u);
}
// Split v into (hi, lo) bf16; returns packed hi pair, writes packed lo pair.
__device__ __forceinline__ uint32_t split2(float v0, float v1, uint32_t& lo) {
    __nv_bfloat16 h0 = __float2bfloat16(v0);
    __nv_bfloat16 h1 = __float2bfloat16(v1);
    __nv_bfloat16 l0 = __float2bfloat16(v0 - __bfloat162float(h0));
    __nv_bfloat16 l1 = __float2bfloat16(v1 - __bfloat162float(h1));
    lo = ((uint32_t)__bfloat16_as_ushort(l1) << 16) | __bfloat16_as_ushort(l0);
    return ((uint32_t)__bfloat16_as_ushort(h1) << 16) | __bfloat16_as_ushort(h0);
}

#define MMA16(c, a0, a1, a2, a3, b0, b1)                                        \
    asm volatile(                                                               \
        "mma.sync.aligned.m16n8k16.row.col.f32.bf16.bf16.f32 "                  \
        "{%0,%1,%2,%3}, {%4,%5,%6,%7}, {%8,%9}, {%0,%1,%2,%3};"                 \
        : "+f"((c)[0]), "+f"((c)[1]), "+f"((c)[2]), "+f"((c)[3])                \
        : "r"(a0), "r"(a1), "r"(a2), "r"(a3), "r"(b0), "r"(b1))

// One n-half (4 ni) of a 32-k chunk: hi*hi + lo*hi (B hi-plane), then hi*lo.
// Each uint4 fragment serves BOTH k16 windows (.x/.y = window0, .z/.w = window1)
// via the free k-permutation. 48 MMAs per call.
template <int S, int NH>
__device__ __forceinline__ void nh_block(float acc[2][8][4],
                                         const uint4 ah[2][2], const uint4 al[2][2],
                                         uint32_t bhf, uint32_t blf)
{
    uint4 bf[4];
    bf[0] = lds128<S * 32768 + NH * 4096 + 0>(bhf);
    bf[1] = lds128<S * 32768 + NH * 4096 + 1024>(bhf);
    bf[2] = lds128<S * 32768 + NH * 4096 + 2048>(bhf);
    bf[3] = lds128<S * 32768 + NH * 4096 + 3072>(bhf);
    // hi*hi window 0
#pragma unroll
    for (int mi = 0; mi < 2; mi++)
#pragma unroll
        for (int nj = 0; nj < 4; nj++)
            MMA16(acc[mi][NH * 4 + nj], ah[mi][0].x, ah[mi][1].x, ah[mi][0].y,
                  ah[mi][1].y, bf[nj].x, bf[nj].y);
    // hi*hi window 1
#pragma unroll
    for (int mi = 0; mi < 2; mi++)
#pragma unroll
        for (int nj = 0; nj < 4; nj++)
            MMA16(acc[mi][NH * 4 + nj], ah[mi][0].z, ah[mi][1].z, ah[mi][0].w,
                  ah[mi][1].w, bf[nj].z, bf[nj].w);
    // lo*hi window 0
#pragma unroll
    for (int mi = 0; mi < 2; mi++)
#pragma unroll
        for (int nj = 0; nj < 4; nj++)
            MMA16(acc[mi][NH * 4 + nj], al[mi][0].x, al[mi][1].x, al[mi][0].y,
                  al[mi][1].y, bf[nj].x, bf[nj].y);
    // lo*hi window 1
#pragma unroll
    for (int mi = 0; mi < 2; mi++)
#pragma unroll
        for (int nj = 0; nj < 4; nj++)
            MMA16(acc[mi][NH * 4 + nj], al[mi][0].z, al[mi][1].z, al[mi][0].w,
                  al[mi][1].w, bf[nj].z, bf[nj].w);
    // reload B lo-plane into the same regs
    bf[0] = lds128<S * 32768 + NH * 4096 + 0>(blf);
    bf[1] = lds128<S * 32768 + NH * 4096 + 1024>(blf);
    bf[2] = lds128<S * 32768 + NH * 4096 + 2048>(blf);
    bf[3] = lds128<S * 32768 + NH * 4096 + 3072>(blf);
    // hi*lo window 0 + 1
#pragma unroll
    for (int mi = 0; mi < 2; mi++)
#pragma unroll
        for (int nj = 0; nj < 4; nj++)
            MMA16(acc[mi][NH * 4 + nj], ah[mi][0].x, ah[mi][1].x, ah[mi][0].y,
                  ah[mi][1].y, bf[nj].x, bf[nj].y);
#pragma unroll
    for (int mi = 0; mi < 2; mi++)
#pragma unroll
        for (int nj = 0; nj < 4; nj++)
            MMA16(acc[mi][NH * 4 + nj], ah[mi][0].z, ah[mi][1].z, ah[mi][0].w,
                  ah[mi][1].w, bf[nj].z, bf[nj].w);
}

template <int S>
__device__ __forceinline__ void chunk_mma(float acc[2][8][4],
                                          uint32_t ahf, uint32_t alf,
                                          uint32_t bhf, uint32_t blf)
{
    uint4 ah[2][2], al[2][2];
    ah[0][0] = lds128<S * 32768 + 0>(ahf);
    ah[0][1] = lds128<S * 32768 + 1024>(ahf);
    ah[1][0] = lds128<S * 32768 + 2048>(ahf);
    ah[1][1] = lds128<S * 32768 + 3072>(ahf);
    al[0][0] = lds128<S * 32768 + 0>(alf);
    al[0][1] = lds128<S * 32768 + 1024>(alf);
    al[1][0] = lds128<S * 32768 + 2048>(alf);
    al[1][1] = lds128<S * 32768 + 3072>(alf);
    nh_block<S, 0>(acc, ah, al, bhf, blf);
    nh_block<S, 1>(acc, ah, al, bhf, blf);
}

// ---------------------------------------------------------------------------
// Split-bf16 mma.sync GEMM: C[M,N] = epilogue(A[M,K] @ B^T + bias)
// A, B in split format. CTA tile 128x128, BK=32, 256 threads / 8 warps,
// 32x64 warp tiles, 2-stage cp.async double buffer, compile-time stages.
// Requires NC = K/32 even.
// MODE 1: C (split) = relu(v + bias[n])
// MODE 2: C (split) = gates[m][z] * relu(v + bias[n])
// MODE 3: C (fp32)  = v + sum_e gates[m][e] * eb3[e][n]  (bias = eb3 flat 8x256)
// ---------------------------------------------------------------------------
template <int MODE>
__global__ __launch_bounds__(256, 2)
void mm_bf16(const float* __restrict__ A, const float* __restrict__ Bw,
             const float* __restrict__ bias, float* __restrict__ C,
             int K, int LDA, int LDC,
             long aStrE, long bStrE, long cStrE, int biasStrE,
             const float* __restrict__ gates)
{
    extern __shared__ char smem[];                 // 2 * (16KB A + 16KB B)
    __shared__ float bias_s[MODE == 3 ? 2048 : 128];

    const int tid  = threadIdx.x;
    const int lane = tid & 31;
    const int warp = tid >> 5;
    const int z = blockIdx.z;
    A    += (size_t)z * aStrE;
    Bw   += (size_t)z * bStrE;
    C    += (size_t)z * cStrE;
    bias += (size_t)z * biasStrE;
    const int m0 = blockIdx.y * 128;
    const int n0 = blockIdx.x * 128;

    if (MODE == 3) {
        for (int i = tid; i < 2048; i += 256) bias_s[i] = bias[i];
    } else {
        if (tid < 128) bias_s[tid] = bias[n0 + tid];
    }

    const uint32_t sb = (uint32_t)__cvta_generic_to_shared(smem);
    const int NC = K >> 5;

    // ---- loader precompute (identical structure to the tf32 kernel) ----
    const uint32_t lr  = tid >> 1;
    const uint32_t lch = (tid & 1) * 4;
    const uint32_t lfp = fperm(lr);
    uint32_t sA[4];
#pragma unroll
    for (int c = 0; c < 4; c++)
        sA[c] = sb + lr * 128 + (((lch + c) ^ lfp) << 4);
    const float* gA = A + (size_t)(m0 + lr) * LDA + lch * 4;
    const float* gB = Bw + (size_t)(n0 + lr) * K + lch * 4;

    // ---- fragment addresses: plane hi = base, plane lo = base ^ 64 ----
    const int wm = (warp & 3) * 32;
    const int wn = (warp >> 2) * 64;
    const int gr = lane >> 2;
    const int gc = lane & 3;
    const uint32_t ahf = sb + ((((uint32_t)(wm + gr)) * 8 +
                                ((uint32_t)gc ^ fperm(wm + gr))) << 4);
    const uint32_t bhf = sb + 16384 + ((((uint32_t)(wn + gr)) * 8 +
                                ((uint32_t)gc ^ fperm(wn + gr))) << 4);
    const uint32_t alf = ahf ^ 64;
    const uint32_t blf = bhf ^ 64;

    float acc[2][8][4];
#pragma unroll
    for (int mi = 0; mi < 2; mi++)
#pragma unroll
        for (int ni = 0; ni < 8; ni++)
#pragma unroll
            for (int t = 0; t < 4; t++) acc[mi][ni][t] = 0.0f;

    // ---- prologue ----
#pragma unroll
    for (int c = 0; c < 4; c++) {
        cpa16(sA[c],  gA + c * 4);
        cpa16b(sA[c], gB + c * 4);
    }
    asm volatile("cp.async.commit_group;" ::: "memory");
    gA += 32; gB += 32;

    // ---- main loop ----
    for (int i = 0; i < NC; i += 2) {
        asm volatile("cp.async.wait_group 0;" ::: "memory");
        __syncthreads();
#pragma unroll
        for (int c = 0; c < 4; c++) {
            cpa16(sA[c] + 32768,  gA + c * 4);
            cpa16b(sA[c] + 32768, gB + c * 4);
        }
        asm volatile("cp.async.commit_group;" ::: "memory");
        gA += 32; gB += 32;
        chunk_mma<0>(acc, ahf, alf, bhf, blf);

        asm volatile("cp.async.wait_group 0;" ::: "memory");
        __syncthreads();
        if (i + 2 < NC) {
#pragma unroll
            for (int c = 0; c < 4; c++) {
                cpa16(sA[c],  gA + c * 4);
                cpa16b(sA[c], gB + c * 4);
            }
            asm volatile("cp.async.commit_group;" ::: "memory");
            gA += 32; gB += 32;
        }
        chunk_mma<1>(acc, ahf, alf, bhf, blf);
    }

    // ---- epilogue ----
#pragma unroll
    for (int mi = 0; mi < 2; mi++) {
        const int r0 = m0 + wm + mi * 16 + gr;
        const int r1 = r0 + 8;
        float gv0 = 0.f, gv1 = 0.f;
        float g8a[8], g8b[8];
        if (MODE == 2) {
            gv0 = gates[(size_t)r0 * 8 + z];
            gv1 = gates[(size_t)r1 * 8 + z];
        }
        if (MODE == 3) {
#pragma unroll
            for (int e = 0; e < 8; e++) {
                g8a[e] = gates[(size_t)r0 * 8 + e];
                g8b[e] = gates[(size_t)r1 * 8 + e];
            }
        }
#pragma unroll
        for (int ni = 0; ni < 8; ni++) {
            const int col  = wn + ni * 8 + 2 * gc;
            const int gcol = n0 + col;
            float v[4];
#pragma unroll
            for (int t = 0; t < 4; t++) v[t] = acc[mi][ni][t];

            if (MODE == 3) {
#pragma unroll
                for (int e = 0; e < 8; e++) {
                    const float b0 = bias_s[e * 256 + gcol];
                    const float b1 = bias_s[e * 256 + gcol + 1];
                    v[0] = fmaf(g8a[e], b0, v[0]);
                    v[1] = fmaf(g8a[e], b1, v[1]);
                    v[2] = fmaf(g8b[e], b0, v[2]);
                    v[3] = fmaf(g8b[e], b1, v[3]);
                }
                *reinterpret_cast<float2*>(&C[(size_t)r0 * LDC + gcol]) = make_float2(v[0], v[1]);
                *reinterpret_cast<float2*>(&C[(size_t)r1 * LDC + gcol]) = make_float2(v[2], v[3]);
            } else {
                v[0] = fmaxf(v[0] + bias_s[col],     0.f);
                v[1] = fmaxf(v[1] + bias_s[col + 1], 0.f);
                v[2] = fmaxf(v[2] + bias_s[col],     0.f);
                v[3] = fmaxf(v[3] + bias_s[col + 1], 0.f);
                if (MODE == 2) { v[0] *= gv0; v[1] *= gv0; v[2] *= gv1; v[3] *= gv1; }
                uint32_t lo01, lo23;
                const uint32_t hi01 = split2(v[0], v[1], lo01);
                const uint32_t hi23 = split2(v[2], v[3], lo23);
                uint8_t* Cb = (uint8_t*)C;
                const size_t blk = (size_t)((gcol >> 5) << 7) + ((gcol & 31) << 1);
                uint8_t* p0 = Cb + (size_t)r0 * LDC * 4 + blk;
                uint8_t* p1 = Cb + (size_t)r1 * LDC * 4 + blk;
                *(uint32_t*)(p0)      = hi01;
                *(uint32_t*)(p0 + 64) = lo01;
                *(uint32_t*)(p1)      = hi23;
                *(uint32_t*)(p1 + 64) = lo23;
            }
        }
    }
}

// ---------------------------------------------------------------------------
// Prep kernels
// ---------------------------------------------------------------------------
// fp32 row-major -> split format (8 elements per thread).
__global__ void k_split(const float4* __restrict__ in, uint8_t* __restrict__ out,
                        int Kd, int n8) {
    const int i = blockIdx.x * 256 + threadIdx.x;
    if (i >= n8) return;
    const float4 v0 = in[2 * i];
    const float4 v1 = in[2 * i + 1];
    uint4 H, L;
    H.x = split2(v0.x, v0.y, L.x);
    H.y = split2(v0.z, v0.w, L.y);
    H.z = split2(v1.x, v1.y, L.z);
    H.w = split2(v1.z, v1.w, L.w);
    const int kper = Kd >> 3;
    const int r = i / kper;
    const int k = (i - r * kper) << 3;
    const size_t base = (size_t)r * Kd * 4 + (size_t)(k >> 5) * 128 + ((k & 31) << 1);
    *reinterpret_cast<uint4*>(out + base)      = H;
    *reinterpret_cast<uint4*>(out + base + 64) = L;
}

__device__ __forceinline__ void store_split(uint8_t* out, int LDO, int b, int a, float v) {
    __nv_bfloat16 h = __float2bfloat16(v);
    __nv_bfloat16 l = __float2bfloat16(v - __bfloat162float(h));
    const size_t base = (size_t)b * LDO * 4 + (size_t)((a >> 5) << 7) + ((a & 31) << 1);
    *reinterpret_cast<unsigned short*>(out + base)      = __bfloat16_as_ushort(h);
    *reinterpret_cast<unsigned short*>(out + base + 64) = __bfloat16_as_ushort(l);
}

// transpose + split: out[b][a] = in[a*Bdim + b]; z-batched (ew1 -> w1cat)
__global__ void k_transpose_s(const float* __restrict__ in, uint8_t* __restrict__ out,
                              int Adim, int Bdim, int LDO, long inStrE, long outStrEBytes) {
    __shared__ float t[32][33];
    in  += (size_t)blockIdx.z * inStrE;
    out += (size_t)blockIdx.z * outStrEBytes;
    const int a0 = blockIdx.y * 32, b0 = blockIdx.x * 32;
    const int x = threadIdx.x, y = threadIdx.y;
    for (int yy = y; yy < 32; yy += 8) {
        const int a = a0 + yy, b = b0 + x;
        t[yy][x] = (a < Adim && b < Bdim) ? in[(size_t)a * Bdim + b] : 0.f;
    }
    __syncthreads();
    for (int yy = y; yy < 32; yy += 8) {
        const int b = b0 + yy, a = a0 + x;
        if (b < Bdim && a < Adim) store_split(out, LDO, b, a, t[x][yy]);
    }
}

// Merged transpose+split for remaining weights, z-dispatched:
//   z == 0      : gw1  [1024,256]  -> gw1t  (LDO 1024)
//   z == 1      : gw2  [256,128]   -> gw2t  (LDO 256)
//   z in [2,10) : ew2[e] [512,512] -> w2t (byte off e*512*512*4, LDO 512)
//   z in [10,18): ew3[e] [512,256] -> w3cat (col off e*512, LDO 4096)
__global__ void k_transpose_rest(const float* __restrict__ gw1,
                                 const float* __restrict__ gw2,
                                 const float* __restrict__ ew2,
                                 const float* __restrict__ ew3,
                                 uint8_t* __restrict__ gw1t,
                                 uint8_t* __restrict__ gw2t,
                                 uint8_t* __restrict__ w2t,
                                 uint8_t* __restrict__ w3cat) {
    __shared__ float t[32][33];
    const int z = blockIdx.z;
    const float* in; uint8_t* out; int Adim, Bdim, LDO, aoff = 0;
    if (z == 0)      { in = gw1; out = gw1t; Adim = 1024; Bdim = 256; LDO = 1024; }
    else if (z == 1) { in = gw2; out = gw2t; Adim = 256;  Bdim = 128; LDO = 256;  }
    else if (z < 10) { const int e = z - 2;  in = ew2 + (size_t)e * 512 * 512;
                       out = w2t + (size_t)e * 512 * 512 * 4; Adim = 512; Bdim = 512; LDO = 512; }
    else             { const int e = z - 10; in = ew3 + (size_t)e * 512 * 256;
                       out = w3cat; aoff = e * 512; Adim = 512; Bdim = 256; LDO = 4096; }

    const int a0 = blockIdx.y * 32, b0 = blockIdx.x * 32;
    if (a0 >= Adim || b0 >= Bdim) return;
    const int x = threadIdx.x, y = threadIdx.y;
    for (int yy = y; yy < 32; yy += 8) {
        const int a = a0 + yy, b = b0 + x;
        t[yy][x] = (a < Adim && b < Bdim) ? in[(size_t)a * Bdim + b] : 0.f;
    }
    __syncthreads();
    for (int yy = y; yy < 32; yy += 8) {
        const int b = b0 + yy, a = a0 + x;
        if (b < Bdim && a < Adim) store_split(out, LDO, b, a + aoff, t[x][yy]);
    }
}

// ---------------------------------------------------------------------------
// Gating final layer + softmax (g2 in split format)
// ---------------------------------------------------------------------------
__global__ void gate_softmax_kernel(const uint8_t* __restrict__ g2,
                                    const float* __restrict__ gw3,
                                    const float* __restrict__ gb3,
                                    float* __restrict__ gates)
{
    __shared__ float ws[128 * 8];
    __shared__ float bs[8];
    const int tid = threadIdx.x;
    for (int i = tid; i < 128 * 8; i += 256) ws[i] = gw3[i];
    if (tid < 8) bs[tid] = gb3[tid];
    __syncthreads();

    const int warp = tid >> 5, lane = tid & 31;
    const int token = blockIdx.x * 8 + warp;
    const uint8_t* xr = g2 + (size_t)token * 512;
    float acc[E_NUM];
#pragma unroll
    for (int e = 0; e < E_NUM; e++) acc[e] = 0.0f;
#pragma unroll
    for (int q = 0; q < 4; q++) {
        const int k = lane + 32 * q;
        const float hv = __bfloat162float(
            *reinterpret_cast<const __nv_bfloat16*>(xr + q * 128 + lane * 2));
        const float lv = __bfloat162float(
            *reinterpret_cast<const __nv_bfloat16*>(xr + q * 128 + 64 + lane * 2));
        const float xv = hv + lv;
#pragma unroll
        for (int e = 0; e < E_NUM; e++) acc[e] = fmaf(xv, ws[k * E_NUM + e], acc[e]);
    }
#pragma unroll
    for (int e = 0; e < E_NUM; e++)
#pragma unroll
        for (int off = 16; off > 0; off >>= 1)
            acc[e] += __shfl_xor_sync(0xffffffffu, acc[e], off);
    if (lane == 0) {
        float mx = -1e30f;
#pragma unroll
        for (int e = 0; e < E_NUM; e++) { acc[e] += bs[e]; mx = fmaxf(mx, acc[e]); }
        float s = 0.0f;
#pragma unroll
        for (int e = 0; e < E_NUM; e++) { acc[e] = expf(acc[e] - mx); s += acc[e]; }
        const float inv = 1.0f / s;
        float* gp = gates + (size_t)token * E_NUM;
#pragma unroll
        for (int e = 0; e < E_NUM; e++) gp[e] = acc[e] * inv;
    }
}

// ---------------------------------------------------------------------------
extern "C" void kernel_launch(void* const* d_in, const int* in_sizes, int n_in,
                              void* d_out, int out_size)
{
    const float* x   = (const float*)d_in[0];
    const float* gw1 = (const float*)d_in[1];
    const float* gb1 = (const float*)d_in[2];
    const float* gw2 = (const float*)d_in[3];
    const float* gb2 = (const float*)d_in[4];
    const float* gw3 = (const float*)d_in[5];
    const float* gb3 = (const float*)d_in[6];
    const float* ew1 = (const float*)d_in[7];
    const float* eb1 = (const float*)d_in[8];
    const float* ew2 = (const float*)d_in[9];
    const float* eb2 = (const float*)d_in[10];
    const float* ew3 = (const float*)d_in[11];
    const float* eb3 = (const float*)d_in[12];
    float* out = (float*)d_out;

    uint8_t *xr, *gw1t, *gw2t, *w1cat, *w2t, *w3cat, *g1, *g2, *h1s, *h2s;
    float* gates;
    cudaGetSymbolAddress((void**)&xr, g_xr);
    cudaGetSymbolAddress((void**)&gw1t, g_gw1t);
    cudaGetSymbolAddress((void**)&gw2t, g_gw2t);
    cudaGetSymbolAddress((void**)&w1cat, g_w1cat);
    cudaGetSymbolAddress((void**)&w2t, g_w2t);
    cudaGetSymbolAddress((void**)&w3cat, g_w3cat);
    cudaGetSymbolAddress((void**)&g1, g_g1);
    cudaGetSymbolAddress((void**)&g2, g_g2);
    cudaGetSymbolAddress((void**)&gates, g_gates);
    cudaGetSymbolAddress((void**)&h1s, g_h1s);
    cudaGetSymbolAddress((void**)&h2s, g_h2s);

    const int SMB = 2 * 32768;
    cudaFuncSetAttribute(mm_bf16<1>, cudaFuncAttributeMaxDynamicSharedMemorySize, SMB);
    cudaFuncSetAttribute(mm_bf16<2>, cudaFuncAttributeMaxDynamicSharedMemorySize, SMB);
    cudaFuncSetAttribute(mm_bf16<3>, cudaFuncAttributeMaxDynamicSharedMemorySize, SMB);

    dim3 tpb(32, 8);
    const int n8 = B_TOK * D_IN / 8;
    // The profiler captures the 4th launch — keep the L1 expert GEMM there.
    k_split<<<(n8 + 255) / 256, 256>>>((const float4*)x, xr, D_IN, n8);                    // 1
    k_transpose_s<<<dim3(512 / 32, 1024 / 32, 8), tpb>>>(ew1, w1cat, 1024, 512, 1024,
                                                         1024L * 512, 512L * 1024 * 4);     // 2
    k_transpose_rest<<<dim3(16, 32, 18), tpb>>>(gw1, gw2, ew2, ew3,
                                                gw1t, gw2t, w2t, w3cat);                    // 3

    // L1: [16384,1024] @ [1024->4096] -> h1s (relu+bias, split)                 // 4 (profiled)
    mm_bf16<1><<<dim3(32, 128), 256, SMB>>>((const float*)xr, (const float*)w1cat, eb1,
                                            (float*)h1s, 1024, 1024, 4096,
                                            0, 0, 0, 0, nullptr);

    // ---- gating ----
    mm_bf16<1><<<dim3(2, 128), 256, SMB>>>((const float*)xr, (const float*)gw1t, gb1,
                                           (float*)g1, 1024, 1024, 256,
                                           0, 0, 0, 0, nullptr);
    mm_bf16<1><<<dim3(1, 128), 256, SMB>>>((const float*)g1, (const float*)gw2t, gb2,
                                           (float*)g2, 256, 256, 128,
                                           0, 0, 0, 0, nullptr);
    gate_softmax_kernel<<<B_TOK / 8, 256>>>(g2, gw3, gb3, gates);

    // ---- experts (cont.) ----
    // L2: per-expert [16384,512]@[512,512] -> h2s (gate * relu, split)
    mm_bf16<2><<<dim3(4, 128, 8), 256, SMB>>>((const float*)h1s, (const float*)w2t, eb2,
                                              (float*)h2s, 512, 4096, 4096,
                                              512, 512L * 512, 512, 512, gates);
    // L3: [16384,4096] @ [4096,256] -> out fp32 (+ gate-weighted eb3)
    mm_bf16<3><<<dim3(2, 128), 256, SMB>>>((const float*)h2s, (const float*)w3cat, eb3,
                                           out, 4096, 4096, 256,
                                           0, 0, 0, 0, gates);
}

// round 17
// speedup vs baseline: 1.3216x; 1.3216x over previous
#include <cuda_runtime.h>
#include <math.h>
#include <stdint.h>

#define B_TOK 16384
#define D_IN  1024
#define H_DIM 512
#define O_DIM 256
#define E_NUM 8

// ---------------------------------------------------------------------------
// Scratch (__device__ globals; no allocation allowed)
// ---------------------------------------------------------------------------
__device__ float g_xr[(size_t)B_TOK * D_IN];            // x, tf32-rounded
__device__ float g_gw1t[256 * 1024];                    // [n][k]
__device__ float g_gw2t[128 * 256];
__device__ float g_w1cat[(size_t)E_NUM * 512 * 1024];   // [e*512+h][d]
__device__ float g_w2t[(size_t)E_NUM * 512 * 512];      // per-e [h_out][h_in]
__device__ float g_w3cat[(size_t)256 * 4096];           // [o][e*512+h]
__device__ float g_g1[(size_t)B_TOK * 256];
__device__ float g_gates[(size_t)B_TOK * 8];
__device__ float g_h1s[(size_t)B_TOK * 4096];
__device__ float g_h2s[(size_t)B_TOK * 4096];

// ---------------------------------------------------------------------------
// Helpers
// ---------------------------------------------------------------------------
__device__ __forceinline__ float tf32r(float x) {
    float y;
    asm("cvt.rna.tf32.f32 %0, %1;" : "=f"(y) : "f"(x));
    return y;
}
__device__ __forceinline__ void cpa16(uint32_t d, const void* s) {
    asm volatile("cp.async.cg.shared.global [%0], [%1], 16;" :: "r"(d), "l"(s));
}
__device__ __forceinline__ void cpa16b(uint32_t d, const void* s) {
    asm volatile("cp.async.cg.shared.global [%0+16384], [%1], 16;" :: "r"(d), "l"(s));
}
template <int IMM>
__device__ __forceinline__ uint4 lds128(uint32_t addr) {
    uint4 v;
    asm volatile("ld.shared.v4.u32 {%0,%1,%2,%3}, [%4+%5];"
                 : "=r"(v.x), "=r"(v.y), "=r"(v.z), "=r"(v.w)
                 : "r"(addr), "n"(IMM));
    return v;
}
// Per-row 16B-chunk permutation; fperm(r+8) == fperm(r) so fragment addresses
// for all row-steps (multiples of 8) share one register + immediates.
__device__ __forceinline__ uint32_t fperm(uint32_t r) {
    return ((r & 1u) << 2) | ((r >> 1) & 3u);
}

#define MMA8(c, a0, a1, a2, a3, b0, b1)                                         \
    asm volatile(                                                               \
        "mma.sync.aligned.m16n8k8.row.col.f32.tf32.tf32.f32 "                   \
        "{%0,%1,%2,%3}, {%4,%5,%6,%7}, {%8,%9}, {%0,%1,%2,%3};"                 \
        : "+f"((c)[0]), "+f"((c)[1]), "+f"((c)[2]), "+f"((c)[3])                \
        : "r"(a0), "r"(a1), "r"(a2), "r"(a3), "r"(b0), "r"(b1))

// One 32-k chunk of MMAs for stage S (exact R11/R15 structure — best measured).
template <int S>
__device__ __forceinline__ void chunk_mma(float acc[2][8][4],
                                          uint32_t aoff0, uint32_t aoff1,
                                          uint32_t boff0, uint32_t boff1)
{
#pragma unroll
    for (int p = 0; p < 2; p++) {
        const uint32_t ao = p ? aoff1 : aoff0;
        const uint32_t bo = p ? boff1 : boff0;
        uint4 af[2][2];
        af[0][0] = lds128<S * 32768 + 0 * 2048 + 0 * 1024>(ao);
        af[0][1] = lds128<S * 32768 + 0 * 2048 + 1 * 1024>(ao);
        af[1][0] = lds128<S * 32768 + 1 * 2048 + 0 * 1024>(ao);
        af[1][1] = lds128<S * 32768 + 1 * 2048 + 1 * 1024>(ao);
        uint4 bf[8];
        bf[0] = lds128<S * 32768 + 0 * 1024>(bo);
        bf[1] = lds128<S * 32768 + 1 * 1024>(bo);
        bf[2] = lds128<S * 32768 + 2 * 1024>(bo);
        bf[3] = lds128<S * 32768 + 3 * 1024>(bo);
        bf[4] = lds128<S * 32768 + 4 * 1024>(bo);
        bf[5] = lds128<S * 32768 + 5 * 1024>(bo);
        bf[6] = lds128<S * 32768 + 6 * 1024>(bo);
        bf[7] = lds128<S * 32768 + 7 * 1024>(bo);
#pragma unroll
        for (int mi = 0; mi < 2; mi++)
#pragma unroll
            for (int ni = 0; ni < 8; ni++)
                MMA8(acc[mi][ni], af[mi][0].x, af[mi][1].x, af[mi][0].y,
                     af[mi][1].y, bf[ni].x, bf[ni].y);
#pragma unroll
        for (int mi = 0; mi < 2; mi++)
#pragma unroll
            for (int ni = 0; ni < 8; ni++)
                MMA8(acc[mi][ni], af[mi][0].z, af[mi][1].z, af[mi][0].w,
                     af[mi][1].w, bf[ni].z, bf[ni].w);
    }
}

// ---------------------------------------------------------------------------
// tf32 mma.sync GEMM: C[M,N] = epilogue(A[M,K] @ B^T + bias)
// B is K-major [N][K]. CTA tile 128x128, BK=32, 256 threads / 8 warps with
// 32x64 warp tiles. 2-stage cp.async double buffer, loop unrolled x2 so the
// stage index is compile-time. Requires NC = K/32 even.
// MODE 1: C = tf32(relu(v + bias[n]))
// MODE 2: C = tf32(gates[m][z] * relu(v + bias[n]))
// MODE 3: C = v + sum_e gates[m][e] * eb3[e][n]   (bias carries eb3 flat 8x256)
// MODE 4: gating L2 + fused softmax: g2 = relu(v + bias) kept in smem only;
//         gates[m][:] = softmax(g2[m] @ gw3p + gb3p). Requires N == 128
//         (one CTA holds complete token rows). C is not written.
// ---------------------------------------------------------------------------
template <int MODE>
__global__ __launch_bounds__(256, 2)
void mm_tf32(const float* __restrict__ A, const float* __restrict__ Bw,
             const float* __restrict__ bias, float* __restrict__ C,
             int K, int LDA, int LDC,
             long aStrE, long bStrE, long cStrE, int biasStrE,
             const float* __restrict__ gates,
             const float* __restrict__ gw3p, const float* __restrict__ gb3p)
{
    extern __shared__ char smem[];                 // >= 2 * (16KB A + 16KB B)
    __shared__ float bias_s[MODE == 3 ? 2048 : 128];

    const int tid  = threadIdx.x;
    const int lane = tid & 31;
    const int warp = tid >> 5;
    const int z = blockIdx.z;
    A    += (size_t)z * aStrE;
    Bw   += (size_t)z * bStrE;
    C    += (size_t)z * cStrE;
    bias += (size_t)z * biasStrE;
    const int m0 = blockIdx.y * 128;
    const int n0 = blockIdx.x * 128;

    if (MODE == 3) {
        for (int i = tid; i < 2048; i += 256) bias_s[i] = bias[i];
    } else {
        if (tid < 128) bias_s[tid] = bias[n0 + tid];
    }

    const uint32_t sb = (uint32_t)__cvta_generic_to_shared(smem);
    const int NC = K >> 5;

    // ---- loader precompute (256 threads: row r = tid>>1, 4 chunks each) ----
    const uint32_t lr  = tid >> 1;
    const uint32_t lch = (tid & 1) * 4;
    const uint32_t lfp = fperm(lr);
    uint32_t sA[4];
#pragma unroll
    for (int c = 0; c < 4; c++)
        sA[c] = sb + lr * 128 + (((lch + c) ^ lfp) << 4);
    const float* gA = A + (size_t)(m0 + lr) * LDA + lch * 4;
    const float* gB = Bw + (size_t)(n0 + lr) * K + lch * 4;

    // ---- fragment address precompute (4 registers total) ----
    const int wm = (warp & 3) * 32;
    const int wn = (warp >> 2) * 64;
    const int gr = lane >> 2;
    const int gc = lane & 3;
    const uint32_t aoff0 = sb + ((((uint32_t)(wm + gr)) * 8 +
                                  ((uint32_t)gc ^ fperm(wm + gr))) << 4);
    const uint32_t boff0 = sb + 16384 + ((((uint32_t)(wn + gr)) * 8 +
                                  ((uint32_t)gc ^ fperm(wn + gr))) << 4);
    const uint32_t aoff1 = aoff0 ^ 64;
    const uint32_t boff1 = boff0 ^ 64;

    float acc[2][8][4];
#pragma unroll
    for (int mi = 0; mi < 2; mi++)
#pragma unroll
        for (int ni = 0; ni < 8; ni++)
#pragma unroll
            for (int t = 0; t < 4; t++) acc[mi][ni][t] = 0.0f;

    // ---- prologue: load chunk 0 into stage 0 ----
#pragma unroll
    for (int c = 0; c < 4; c++) {
        cpa16(sA[c],  gA + c * 4);
        cpa16b(sA[c], gB + c * 4);
    }
    asm volatile("cp.async.commit_group;" ::: "memory");
    gA += 32; gB += 32;

    // ---- main loop: 2 chunks per iteration, compile-time stages ----
    for (int i = 0; i < NC; i += 2) {
        asm volatile("cp.async.wait_group 0;" ::: "memory");
        __syncthreads();
#pragma unroll
        for (int c = 0; c < 4; c++) {
            cpa16(sA[c] + 32768,  gA + c * 4);
            cpa16b(sA[c] + 32768, gB + c * 4);
        }
        asm volatile("cp.async.commit_group;" ::: "memory");
        gA += 32; gB += 32;
        chunk_mma<0>(acc, aoff0, aoff1, boff0, boff1);

        asm volatile("cp.async.wait_group 0;" ::: "memory");
        __syncthreads();
        if (i + 2 < NC) {
#pragma unroll
            for (int c = 0; c < 4; c++) {
                cpa16(sA[c],  gA + c * 4);
                cpa16b(sA[c], gB + c * 4);
            }
            asm volatile("cp.async.commit_group;" ::: "memory");
            gA += 32; gB += 32;
        }
        chunk_mma<1>(acc, aoff0, aoff1, boff0, boff1);
    }

    if (MODE == 4) {
        // ---- fused gating epilogue: smem g2 + per-warp softmax ----
        float* g2s = (float*)smem;                  // [128][stride 132] floats
        __syncthreads();                            // all warps done with stages
#pragma unroll
        for (int mi = 0; mi < 2; mi++) {
            const int r0l = wm + mi * 16 + gr;
#pragma unroll
            for (int ni = 0; ni < 8; ni++) {
                const int col = wn + ni * 8 + 2 * gc;
                g2s[r0l * 132 + col]           = fmaxf(acc[mi][ni][0] + bias_s[col],     0.f);
                g2s[r0l * 132 + col + 1]       = fmaxf(acc[mi][ni][1] + bias_s[col + 1], 0.f);
                g2s[(r0l + 8) * 132 + col]     = fmaxf(acc[mi][ni][2] + bias_s[col],     0.f);
                g2s[(r0l + 8) * 132 + col + 1] = fmaxf(acc[mi][ni][3] + bias_s[col + 1], 0.f);
            }
        }
        __syncthreads();
        // per-lane gw3 rows k = lane, lane+32, lane+64, lane+96
        float ws[4][8];
#pragma unroll
        for (int q = 0; q < 4; q++)
#pragma unroll
            for (int e = 0; e < 8; e++)
                ws[q][e] = gw3p[(lane + 32 * q) * 8 + e];
        float bs[8];
#pragma unroll
        for (int e = 0; e < 8; e++) bs[e] = gb3p[e];

        float* gout = (float*)gates;  // gates used as OUTPUT in MODE 4
        for (int tt = 0; tt < 16; tt++) {
            const int t = warp * 16 + tt;
            float a8[8];
#pragma unroll
            for (int e = 0; e < 8; e++) a8[e] = 0.f;
#pragma unroll
            for (int q = 0; q < 4; q++) {
                const float xv = g2s[t * 132 + lane + 32 * q];
#pragma unroll
                for (int e = 0; e < 8; e++) a8[e] = fmaf(xv, ws[q][e], a8[e]);
            }
#pragma unroll
            for (int e = 0; e < 8; e++)
#pragma unroll
                for (int off = 16; off > 0; off >>= 1)
                    a8[e] += __shfl_xor_sync(0xffffffffu, a8[e], off);
            if (lane == 0) {
                float mx = -1e30f;
#pragma unroll
                for (int e = 0; e < 8; e++) { a8[e] += bs[e]; mx = fmaxf(mx, a8[e]); }
                float s = 0.f;
#pragma unroll
                for (int e = 0; e < 8; e++) { a8[e] = expf(a8[e] - mx); s += a8[e]; }
                const float inv = 1.f / s;
                float* gp = gout + (size_t)(m0 + t) * 8;
#pragma unroll
                for (int e = 0; e < 8; e++) gp[e] = a8[e] * inv;
            }
        }
        return;
    }

    // ---- standard epilogue (MODE 1/2/3) ----
#pragma unroll
    for (int mi = 0; mi < 2; mi++) {
        const int r0 = m0 + wm + mi * 16 + gr;
        const int r1 = r0 + 8;
        float gv0 = 0.f, gv1 = 0.f;
        float g8a[8], g8b[8];
        if (MODE == 2) {
            gv0 = gates[(size_t)r0 * 8 + z];
            gv1 = gates[(size_t)r1 * 8 + z];
        }
        if (MODE == 3) {
#pragma unroll
            for (int e = 0; e < 8; e++) {
                g8a[e] = gates[(size_t)r0 * 8 + e];
                g8b[e] = gates[(size_t)r1 * 8 + e];
            }
        }
#pragma unroll
        for (int ni = 0; ni < 8; ni++) {
            const int col  = wn + ni * 8 + 2 * gc;
            const int gcol = n0 + col;
            float v[4];
#pragma unroll
            for (int t = 0; t < 4; t++) v[t] = acc[mi][ni][t];

            if (MODE == 3) {
#pragma unroll
                for (int e = 0; e < 8; e++) {
                    const float b0 = bias_s[e * 256 + gcol];
                    const float b1 = bias_s[e * 256 + gcol + 1];
                    v[0] = fmaf(g8a[e], b0, v[0]);
                    v[1] = fmaf(g8a[e], b1, v[1]);
                    v[2] = fmaf(g8b[e], b0, v[2]);
                    v[3] = fmaf(g8b[e], b1, v[3]);
                }
            } else {
                v[0] = fmaxf(v[0] + bias_s[col],     0.f);
                v[1] = fmaxf(v[1] + bias_s[col + 1], 0.f);
                v[2] = fmaxf(v[2] + bias_s[col],     0.f);
                v[3] = fmaxf(v[3] + bias_s[col + 1], 0.f);
                if (MODE == 2) { v[0] *= gv0; v[1] *= gv0; v[2] *= gv1; v[3] *= gv1; }
                v[0] = tf32r(v[0]); v[1] = tf32r(v[1]);
                v[2] = tf32r(v[2]); v[3] = tf32r(v[3]);
            }
            *reinterpret_cast<float2*>(&C[(size_t)r0 * LDC + gcol]) = make_float2(v[0], v[1]);
            *reinterpret_cast<float2*>(&C[(size_t)r1 * LDC + gcol]) = make_float2(v[2], v[3]);
        }
    }
}

// ---------------------------------------------------------------------------
// Prep kernels (exact R15)
// ---------------------------------------------------------------------------
__global__ void k_round4(const float4* __restrict__ in, float4* __restrict__ out, int n4) {
    const int i = blockIdx.x * 256 + threadIdx.x;
    if (i < n4) {
        float4 v = in[i];
        v.x = tf32r(v.x); v.y = tf32r(v.y); v.z = tf32r(v.z); v.w = tf32r(v.w);
        out[i] = v;
    }
}

__global__ void k_transpose_r(const float* __restrict__ in, float* __restrict__ out,
                              int Adim, int Bdim, int LDO, long inStrE, long outStrE) {
    __shared__ float t[32][33];
    in  += (size_t)blockIdx.z * inStrE;
    out += (size_t)blockIdx.z * outStrE;
    const int a0 = blockIdx.y * 32, b0 = blockIdx.x * 32;
    const int x = threadIdx.x, y = threadIdx.y;
    for (int yy = y; yy < 32; yy += 8) {
        const int a = a0 + yy, b = b0 + x;
        t[yy][x] = (a < Adim && b < Bdim) ? in[(size_t)a * Bdim + b] : 0.f;
    }
    __syncthreads();
    for (int yy = y; yy < 32; yy += 8) {
        const int b = b0 + yy, a = a0 + x;
        if (b < Bdim && a < Adim) out[(size_t)b * LDO + a] = tf32r(t[x][yy]);
    }
}

__global__ void k_transpose_rest(const float* __restrict__ gw1,
                                 const float* __restrict__ gw2,
                                 const float* __restrict__ ew2,
                                 const float* __restrict__ ew3,
                                 float* __restrict__ gw1t,
                                 float* __restrict__ gw2t,
                                 float* __restrict__ w2t,
                                 float* __restrict__ w3cat) {
    __shared__ float t[32][33];
    const int z = blockIdx.z;
    const float* in; float* out; int Adim, Bdim, LDO;
    if (z == 0)      { in = gw1; out = gw1t; Adim = 1024; Bdim = 256; LDO = 1024; }
    else if (z == 1) { in = gw2; out = gw2t; Adim = 256;  Bdim = 128; LDO = 256;  }
    else if (z < 10) { const int e = z - 2;  in = ew2 + (size_t)e * 512 * 512; out = w2t + (size_t)e * 512 * 512; Adim = 512; Bdim = 512; LDO = 512;  }
    else             { const int e = z - 10; in = ew3 + (size_t)e * 512 * 256; out = w3cat + (size_t)e * 512;     Adim = 512; Bdim = 256; LDO = 4096; }

    const int a0 = blockIdx.y * 32, b0 = blockIdx.x * 32;
    if (a0 >= Adim || b0 >= Bdim) return;
    const int x = threadIdx.x, y = threadIdx.y;
    for (int yy = y; yy < 32; yy += 8) {
        const int a = a0 + yy, b = b0 + x;
        t[yy][x] = (a < Adim && b < Bdim) ? in[(size_t)a * Bdim + b] : 0.f;
    }
    __syncthreads();
    for (int yy = y; yy < 32; yy += 8) {
        const int b = b0 + yy, a = a0 + x;
        if (b < Bdim && a < Adim) out[(size_t)b * LDO + a] = tf32r(t[x][yy]);
    }
}

// ---------------------------------------------------------------------------
extern "C" void kernel_launch(void* const* d_in, const int* in_sizes, int n_in,
                              void* d_out, int out_size)
{
    const float* x   = (const float*)d_in[0];
    const float* gw1 = (const float*)d_in[1];
    const float* gb1 = (const float*)d_in[2];
    const float* gw2 = (const float*)d_in[3];
    const float* gb2 = (const float*)d_in[4];
    const float* gw3 = (const float*)d_in[5];
    const float* gb3 = (const float*)d_in[6];
    const float* ew1 = (const float*)d_in[7];
    const float* eb1 = (const float*)d_in[8];
    const float* ew2 = (const float*)d_in[9];
    const float* eb2 = (const float*)d_in[10];
    const float* ew3 = (const float*)d_in[11];
    const float* eb3 = (const float*)d_in[12];
    float* out = (float*)d_out;

    float *xr, *gw1t, *gw2t, *w1cat, *w2t, *w3cat, *g1, *gates, *h1s, *h2s;
    cudaGetSymbolAddress((void**)&xr, g_xr);
    cudaGetSymbolAddress((void**)&gw1t, g_gw1t);
    cudaGetSymbolAddress((void**)&gw2t, g_gw2t);
    cudaGetSymbolAddress((void**)&w1cat, g_w1cat);
    cudaGetSymbolAddress((void**)&w2t, g_w2t);
    cudaGetSymbolAddress((void**)&w3cat, g_w3cat);
    cudaGetSymbolAddress((void**)&g1, g_g1);
    cudaGetSymbolAddress((void**)&gates, g_gates);
    cudaGetSymbolAddress((void**)&h1s, g_h1s);
    cudaGetSymbolAddress((void**)&h2s, g_h2s);

    const int SMB  = 2 * 32768;          // 64 KB (MODE 1/2/3)
    const int SMB4 = 128 * 132 * 4;      // 67584 B (MODE 4: stages + g2 smem)
    cudaFuncSetAttribute(mm_tf32<1>, cudaFuncAttributeMaxDynamicSharedMemorySize, SMB);
    cudaFuncSetAttribute(mm_tf32<2>, cudaFuncAttributeMaxDynamicSharedMemorySize, SMB);
    cudaFuncSetAttribute(mm_tf32<3>, cudaFuncAttributeMaxDynamicSharedMemorySize, SMB);
    cudaFuncSetAttribute(mm_tf32<4>, cudaFuncAttributeMaxDynamicSharedMemorySize, SMB4);

    dim3 tpb(32, 8);
    // The profiler captures the 4th launch — keep the L1 expert GEMM there.
    k_round4<<<(B_TOK * D_IN / 4 + 255) / 256, 256>>>((const float4*)x, (float4*)xr,
                                                      B_TOK * D_IN / 4);                    // 1
    k_transpose_r<<<dim3(512 / 32, 1024 / 32, 8), tpb>>>(ew1, w1cat, 1024, 512, 1024,
                                                         1024L * 512, 512L * 1024);         // 2
    k_transpose_rest<<<dim3(16, 32, 18), tpb>>>(gw1, gw2, ew2, ew3,
                                                gw1t, gw2t, w2t, w3cat);                    // 3

    // L1: [16384,1024] @ [1024->4096] -> h1s (relu+bias, tf32-rounded)          // 4 (profiled)
    mm_tf32<1><<<dim3(32, 128), 256, SMB>>>(xr, w1cat, eb1, h1s, 1024, 1024, 4096,
                                            0, 0, 0, 0, nullptr, nullptr, nullptr);

    // ---- gating ----
    mm_tf32<1><<<dim3(2, 128), 256, SMB>>>(xr, gw1t, gb1, g1, 1024, 1024, 256,
                                           0, 0, 0, 0, nullptr, nullptr, nullptr);
    // gating L2 + fused softmax: writes gates directly (no g2 round-trip)
    mm_tf32<4><<<dim3(1, 128), 256, SMB4>>>(g1, gw2t, gb2, gates, 256, 256, 128,
                                            0, 0, 0, 0, gates, gw3, gb3);

    // ---- experts (cont.) ----
    // L2: per-expert [16384,512]@[512,512] -> h2s (gate * relu, tf32-rounded)
    mm_tf32<2><<<dim3(4, 128, 8), 256, SMB>>>(h1s, w2t, eb2, h2s, 512, 4096, 4096,
                                              512, 512L * 512, 512, 512, gates,
                                              nullptr, nullptr);
    // L3: [16384,4096] @ [4096,256] -> out (+ gate-weighted eb3)
    mm_tf32<3><<<dim3(2, 128), 256, SMB>>>(h2s, w3cat, eb3, out, 4096, 4096, 256,
                                           0, 0, 0, 0, gates, nullptr, nullptr);
}